// round 15
// baseline (speedup 1.0000x reference)
#include <cuda_runtime.h>
#include <cuda_bf16.h>
#include <cuda_fp16.h>

// out[b] = softmax_rows(X_b X_b^T), X: [4, 4096, 64] fp32.
// R11: ONE symmetric GEMM pass. Per 64-col chunk: exact tile max, fp16
//      exp(s - m_chunk) scratch (128MB), (max,sum) float2 partials.
//      scale_rows: log-sum-exp merge of 64 chunks -> per-chunk factors ->
//      fp32 out. No Cauchy-Schwarz shift (caused R10's fp16 underflow).
// mma.sync bf16 3-term hi/lo split; ptxas target sm_103 -> no tcgen05.

#define NTOK 4096
#define DDIM 64
#define NB   4

__device__ __nv_bfloat16 g_hi[(size_t)NB * NTOK * DDIM];   // 4 MB
__device__ __nv_bfloat16 g_lo[(size_t)NB * NTOK * DDIM];   // 4 MB
__device__ float2 g_part[(size_t)NB * NTOK * 64];          // 8 MB (max,sum)
__device__ __half g_E   [(size_t)NB * NTOK * NTOK];        // 128 MB fp16 exp

#define SW128(off) ((off) ^ (((off) >> 3) & 0x70))

// smem: operands Ah@0 Al@16K Bh@32K Bl@40K (to 49152)
// aux:  credm@49152(1K) creds@50176(1K) cmax@51200(256B)
// stage (mirror) reuses [0, 33792)
#define OFF_AL    16384
#define OFF_BH    32768
#define OFF_BL    40960
#define OFF_CREDM 49152
#define OFF_CREDS 50176
#define OFF_CMAX  51200
#define SMEM_BYTES 51712
#define STG_LD 132

__device__ __forceinline__ unsigned smem_u32(const void* p) {
    unsigned a;
    asm("{ .reg .u64 t; cvta.to.shared.u64 t, %1; cvt.u32.u64 %0, t; }"
        : "=r"(a) : "l"(p));
    return a;
}
__device__ __forceinline__ void ldsm4(unsigned* r, unsigned addr) {
    asm volatile("ldmatrix.sync.aligned.m8n8.x4.shared.b16 {%0,%1,%2,%3}, [%4];"
                 : "=r"(r[0]), "=r"(r[1]), "=r"(r[2]), "=r"(r[3]) : "r"(addr));
}
__device__ __forceinline__ void mma16816(float* d, const unsigned* a,
                                         unsigned b0, unsigned b1) {
    asm volatile(
        "mma.sync.aligned.m16n8k16.row.col.f32.bf16.bf16.f32 "
        "{%0,%1,%2,%3}, {%4,%5,%6,%7}, {%8,%9}, {%0,%1,%2,%3};"
        : "+f"(d[0]), "+f"(d[1]), "+f"(d[2]), "+f"(d[3])
        : "r"(a[0]), "r"(a[1]), "r"(a[2]), "r"(a[3]), "r"(b0), "r"(b1));
}

__device__ __forceinline__ void decode_pair(int p, int& ti, int& tj) {
    ti = (int)((65.0f - sqrtf(4225.0f - 8.0f * (float)p)) * 0.5f);
    while (ti * (65 - ti) / 2 > p) ti--;
    while ((ti + 1) * (64 - ti) / 2 <= p) ti++;
    tj = ti + (p - ti * (65 - ti) / 2);
}

// ---------------- split ----------------
__global__ __launch_bounds__(256) void split_bf16(const float* __restrict__ X) {
    size_t i = ((size_t)blockIdx.x * blockDim.x + threadIdx.x) * 4;
    float4 v = *reinterpret_cast<const float4*>(X + i);
    __nv_bfloat162 h01 = __floats2bfloat162_rn(v.x, v.y);
    __nv_bfloat162 h23 = __floats2bfloat162_rn(v.z, v.w);
    __nv_bfloat162 l01 = __floats2bfloat162_rn(v.x - __low2float(h01),
                                               v.y - __high2float(h01));
    __nv_bfloat162 l23 = __floats2bfloat162_rn(v.z - __low2float(h23),
                                               v.w - __high2float(h23));
    *reinterpret_cast<__nv_bfloat162*>(g_hi + i)     = h01;
    *reinterpret_cast<__nv_bfloat162*>(g_hi + i + 2) = h23;
    *reinterpret_cast<__nv_bfloat162*>(g_lo + i)     = l01;
    *reinterpret_cast<__nv_bfloat162*>(g_lo + i + 2) = l23;
}

// ---------------- tile compute ----------------
template<int CH>
__device__ __forceinline__ void load_t(char* dst, const __nv_bfloat16* src, int tid) {
    const uint4* s = reinterpret_cast<const uint4*>(src);
#pragma unroll
    for (int it = 0; it < CH; it++) {
        int i = it * 128 + tid;
        unsigned off = (unsigned)i * 16u;
        *reinterpret_cast<uint4*>(dst + SW128(off)) = s[i];
    }
}

__device__ __forceinline__ void tile_compute(char* smem, unsigned sm, int tid,
                                             int wid, int lane, int ti, int tj,
                                             int half, int b, bool diag,
                                             float acc[2][8][4]) {
    const size_t gti = (size_t)b * NTOK + (size_t)ti * 128;
    const size_t gtj = (size_t)b * NTOK + (size_t)tj * 128 + half * 64;
    load_t<8>(smem,          g_hi + gti * DDIM, tid);
    load_t<8>(smem + OFF_AL, g_lo + gti * DDIM, tid);
    if (!diag) {
        load_t<4>(smem + OFF_BH, g_hi + gtj * DDIM, tid);
        load_t<4>(smem + OFF_BL, g_lo + gtj * DDIM, tid);
    }
    __syncthreads();

#pragma unroll
    for (int mf = 0; mf < 2; mf++)
#pragma unroll
        for (int nf = 0; nf < 8; nf++)
#pragma unroll
            for (int e = 0; e < 4; e++) acc[mf][nf][e] = 0.0f;

    const int mrow0 = wid * 32;
    const int lrow  = lane & 15;
    const int lkoff = (lane >> 4) * 8;
    const unsigned abH = sm, abL = sm + OFF_AL;
    const unsigned bbH = diag ? sm + half * 8192          : sm + OFF_BH;
    const unsigned bbL = diag ? sm + OFF_AL + half * 8192 : sm + OFF_BL;

    unsigned arow[2], axor[2], brow[4], bxor[4];
#pragma unroll
    for (int mf = 0; mf < 2; mf++) {
        arow[mf] = (unsigned)(mrow0 + mf * 16 + lrow) * 128u;
        axor[mf] = (((mrow0 + mf * 16 + lrow) & 7) << 4);
    }
#pragma unroll
    for (int nq = 0; nq < 4; nq++) {
        brow[nq] = (unsigned)(nq * 16 + lrow) * 128u;
        bxor[nq] = (((nq * 16 + lrow) & 7) << 4);
    }

#pragma unroll
    for (int ks = 0; ks < 4; ks++) {
        const unsigned kb = (unsigned)(ks * 16 + lkoff) * 2u;
        unsigned ah[2][4], al[2][4], bh[4][4], bl[4][4];
#pragma unroll
        for (int mf = 0; mf < 2; mf++)
            ldsm4(ah[mf], abH + arow[mf] + (kb ^ axor[mf]));
#pragma unroll
        for (int nq = 0; nq < 4; nq++)
            ldsm4(bh[nq], bbH + brow[nq] + (kb ^ bxor[nq]));
#pragma unroll
        for (int nq = 0; nq < 4; nq++)
#pragma unroll
            for (int mf = 0; mf < 2; mf++) {
                mma16816(acc[mf][nq * 2 + 0], ah[mf], bh[nq][0], bh[nq][2]);
                mma16816(acc[mf][nq * 2 + 1], ah[mf], bh[nq][1], bh[nq][3]);
            }
#pragma unroll
        for (int mf = 0; mf < 2; mf++)
            ldsm4(al[mf], abL + arow[mf] + (kb ^ axor[mf]));
#pragma unroll
        for (int nq = 0; nq < 4; nq++)
            ldsm4(bl[nq], bbL + brow[nq] + (kb ^ bxor[nq]));
#pragma unroll
        for (int nq = 0; nq < 4; nq++)
#pragma unroll
            for (int mf = 0; mf < 2; mf++) {
                mma16816(acc[mf][nq * 2 + 0], ah[mf], bl[nq][0], bl[nq][2]);
                mma16816(acc[mf][nq * 2 + 1], ah[mf], bl[nq][1], bl[nq][3]);
            }
#pragma unroll
        for (int nq = 0; nq < 4; nq++)
#pragma unroll
            for (int mf = 0; mf < 2; mf++) {
                mma16816(acc[mf][nq * 2 + 0], al[mf], bh[nq][0], bh[nq][2]);
                mma16816(acc[mf][nq * 2 + 1], al[mf], bh[nq][1], bh[nq][3]);
            }
    }
}

// ---------------- gemm_exp ----------------
__global__ __launch_bounds__(128, 4) void gemm_exp() {
    int ti, tj;
    decode_pair(blockIdx.x, ti, tj);
    const int half = blockIdx.y, b = blockIdx.z;
    const bool diag = (ti == tj);

    extern __shared__ __align__(1024) char smem[];
    float* stage = reinterpret_cast<float*>(smem);
    const unsigned sm = smem_u32(smem);
    const int tid = threadIdx.x, wid = tid >> 5, lane = tid & 31;

    float acc[2][8][4];
    tile_compute(smem, sm, tid, wid, lane, ti, tj, half, b, diag, acc);

    float* credm = reinterpret_cast<float*>(smem + OFF_CREDM);
    float* creds = reinterpret_cast<float*>(smem + OFF_CREDS);
    float* cmax  = reinterpret_cast<float*>(smem + OFF_CMAX);

    const int mrow0 = wid * 32;
    const int fr = lane >> 2;
    const int fc = (lane & 3) * 2;
    const size_t gti = (size_t)b * NTOK + (size_t)ti * 128;
    const size_t gtj = (size_t)b * NTOK + (size_t)tj * 128 + half * 64;

    // --- row-side: exact 64-col chunk max, fp16 exp store, (max,sum) partial
    {
        float rmx[4];
#pragma unroll
        for (int mf = 0; mf < 2; mf++) {
            float m0 = -1e30f, m1 = -1e30f;
#pragma unroll
            for (int nf = 0; nf < 8; nf++) {
                m0 = fmaxf(m0, fmaxf(acc[mf][nf][0], acc[mf][nf][1]));
                m1 = fmaxf(m1, fmaxf(acc[mf][nf][2], acc[mf][nf][3]));
            }
            rmx[mf * 2] = m0; rmx[mf * 2 + 1] = m1;
        }
#pragma unroll
        for (int k = 0; k < 4; k++) {
            rmx[k] = fmaxf(rmx[k], __shfl_xor_sync(~0u, rmx[k], 1));
            rmx[k] = fmaxf(rmx[k], __shfl_xor_sync(~0u, rmx[k], 2));
        }

        __half* dst = g_E + gti * NTOK + tj * 128 + half * 64;
        float rs[4] = {0.f, 0.f, 0.f, 0.f};
#pragma unroll
        for (int mf = 0; mf < 2; mf++) {
            const int r0 = mrow0 + mf * 16 + fr;
            const float m0 = rmx[mf * 2], m1 = rmx[mf * 2 + 1];
#pragma unroll
            for (int nf = 0; nf < 8; nf++) {
                const int c = nf * 8 + fc;
                float e0 = __expf(acc[mf][nf][0] - m0);
                float e1 = __expf(acc[mf][nf][1] - m0);
                float e2 = __expf(acc[mf][nf][2] - m1);
                float e3 = __expf(acc[mf][nf][3] - m1);
                rs[mf * 2] += e0 + e1; rs[mf * 2 + 1] += e2 + e3;
                *reinterpret_cast<__half2*>(dst + (size_t)r0 * NTOK + c) =
                    __floats2half2_rn(e0, e1);
                *reinterpret_cast<__half2*>(dst + (size_t)(r0 + 8) * NTOK + c) =
                    __floats2half2_rn(e2, e3);
            }
        }
#pragma unroll
        for (int k = 0; k < 4; k++) {
            rs[k] += __shfl_xor_sync(~0u, rs[k], 1);
            rs[k] += __shfl_xor_sync(~0u, rs[k], 2);
        }
        if ((lane & 3) == 0) {
            const int slot = tj * 2 + half;   // in [2*ti, 64)
#pragma unroll
            for (int k = 0; k < 4; k++) {
                int r = mrow0 + (k >> 1) * 16 + fr + (k & 1) * 8;
                g_part[(gti + r) * 64 + slot] = make_float2(rmx[k], rs[k]);
            }
        }
    }

    if (diag) return;

    // --- col-side mirror: tile max over 128 rows, exp stage, split sums ---
    __syncthreads();  // operands dead; aux regions live
    // per-warp column maxima (32 rows each)
#pragma unroll
    for (int nf = 0; nf < 8; nf++) {
        const int c0 = nf * 8 + fc;
        float m0 = fmaxf(fmaxf(acc[0][nf][0], acc[0][nf][2]),
                         fmaxf(acc[1][nf][0], acc[1][nf][2]));
        float m1 = fmaxf(fmaxf(acc[0][nf][1], acc[0][nf][3]),
                         fmaxf(acc[1][nf][1], acc[1][nf][3]));
#pragma unroll
        for (int o = 4; o <= 16; o <<= 1) {
            m0 = fmaxf(m0, __shfl_xor_sync(~0u, m0, o));
            m1 = fmaxf(m1, __shfl_xor_sync(~0u, m1, o));
        }
        if (lane < 4) { credm[wid * 64 + c0] = m0; credm[wid * 64 + c0 + 1] = m1; }
    }
    __syncthreads();
    if (tid < 64)
        cmax[tid] = fmaxf(fmaxf(credm[tid], credm[64 + tid]),
                          fmaxf(credm[128 + tid], credm[192 + tid]));
    __syncthreads();

    // exp with the 128-row tile max; stage fp32; per-warp sums
#pragma unroll
    for (int nf = 0; nf < 8; nf++) {
        const int c0 = nf * 8 + fc;
        const float mc0 = cmax[c0], mc1 = cmax[c0 + 1];
        float p0 = 0.f, p1 = 0.f;
#pragma unroll
        for (int mf = 0; mf < 2; mf++) {
            const int r0 = mrow0 + mf * 16 + fr;
            float e0 = __expf(acc[mf][nf][0] - mc0);
            float e2 = __expf(acc[mf][nf][2] - mc0);
            float e1 = __expf(acc[mf][nf][1] - mc1);
            float e3 = __expf(acc[mf][nf][3] - mc1);
            p0 += e0 + e2; p1 += e1 + e3;
            stage[(size_t)c0 * STG_LD + r0]           = e0;
            stage[(size_t)c0 * STG_LD + r0 + 8]       = e2;
            stage[(size_t)(c0 + 1) * STG_LD + r0]     = e1;
            stage[(size_t)(c0 + 1) * STG_LD + r0 + 8] = e3;
        }
#pragma unroll
        for (int o = 4; o <= 16; o <<= 1) {
            p0 += __shfl_xor_sync(~0u, p0, o);
            p1 += __shfl_xor_sync(~0u, p1, o);
        }
        if (lane < 4) { creds[wid * 64 + c0] = p0; creds[wid * 64 + c0 + 1] = p1; }
    }
    __syncthreads();
    if (tid < 64) {
        // warps 0,1 -> A-rows [0,64) -> slot 2ti; warps 2,3 -> slot 2ti+1
        float sLo = creds[tid] + creds[64 + tid];
        float sHi = creds[128 + tid] + creds[192 + tid];
        float m = cmax[tid];
        g_part[(gtj + tid) * 64 + 2 * ti]     = make_float2(m, sLo);
        g_part[(gtj + tid) * 64 + 2 * ti + 1] = make_float2(m, sHi);
    }
    // fp16 copy-out (coalesced)
    {
        __half* dst = g_E + gtj * NTOK + ti * 128;
        const int c4 = (tid & 31) * 4, rq = tid >> 5;
#pragma unroll
        for (int it = 0; it < 16; it++) {
            const int sr = rq + it * 4;
            float4 v = *reinterpret_cast<const float4*>(
                stage + (size_t)sr * STG_LD + c4);
            *reinterpret_cast<__half2*>(dst + (size_t)sr * NTOK + c4) =
                __floats2half2_rn(v.x, v.y);
            *reinterpret_cast<__half2*>(dst + (size_t)sr * NTOK + c4 + 2) =
                __floats2half2_rn(v.z, v.w);
        }
    }
}

// ---------------- scale_rows: LSE merge + stream out ----------------
__global__ __launch_bounds__(256) void scale_rows(float* __restrict__ out) {
    const size_t row = blockIdx.x;
    const int tid = threadIdx.x, lane = tid & 31;
    const float2* P = g_part + row * 64;

    __shared__ float fac[64];
    __shared__ float redm[2], reds[2];

    if (tid < 64) {
        float m = P[tid].x;
#pragma unroll
        for (int o = 16; o > 0; o >>= 1) m = fmaxf(m, __shfl_xor_sync(~0u, m, o));
        if (lane == 0) redm[tid >> 5] = m;
    }
    __syncthreads();
    const float M = fmaxf(redm[0], redm[1]);
    if (tid < 64) {
        float e = __expf(P[tid].x - M);
        fac[tid] = e;
        float c = P[tid].y * e;
#pragma unroll
        for (int o = 16; o > 0; o >>= 1) c += __shfl_xor_sync(~0u, c, o);
        if (lane == 0) reds[tid >> 5] = c;
    }
    __syncthreads();
    const float invS = 1.0f / (reds[0] + reds[1]);

    const __half* src = g_E + row * NTOK;
    float* dst = out + row * NTOK;
#pragma unroll
    for (int p = 0; p < 2; p++) {
        const int o = p * 2048 + tid * 8;
        const float f = fac[o >> 6] * invS;
        uint4 raw = __ldcs(reinterpret_cast<const uint4*>(src + o));
        const __half2* h = reinterpret_cast<const __half2*>(&raw);
        float2 f0 = __half22float2(h[0]);
        float2 f1 = __half22float2(h[1]);
        float2 f2 = __half22float2(h[2]);
        float2 f3 = __half22float2(h[3]);
        __stcs(reinterpret_cast<float4*>(dst + o),
               make_float4(f0.x * f, f0.y * f, f1.x * f, f1.y * f));
        __stcs(reinterpret_cast<float4*>(dst + o + 4),
               make_float4(f2.x * f, f2.y * f, f3.x * f, f3.y * f));
    }
}

extern "C" void kernel_launch(void* const* d_in, const int* in_sizes, int n_in,
                              void* d_out, int out_size) {
    const float* X = (const float*)d_in[0];
    float* out     = (float*)d_out;
    (void)in_sizes; (void)n_in; (void)out_size;

    cudaFuncSetAttribute(gemm_exp, cudaFuncAttributeMaxDynamicSharedMemorySize,
                         SMEM_BYTES);

    split_bf16<<<1024, 256>>>(X);
    gemm_exp<<<dim3(528, 2, NB), 128, SMEM_BYTES>>>();
    scale_rows<<<NB * NTOK, 256>>>(out);
}

// round 16
// speedup vs baseline: 1.0066x; 1.0066x over previous
#include <cuda_runtime.h>
#include <cuda_bf16.h>
#include <cuda_fp16.h>

// out[b] = softmax_rows(X_b X_b^T), X: [4, 4096, 64] fp32.
// R11: ONE symmetric GEMM pass. Per 64-col chunk: exact tile max, fp16
//      exp(s - m_chunk) scratch (128MB), (max,sum) float2 partials.
//      scale_rows: log-sum-exp merge of 64 chunks -> per-chunk factors ->
//      fp32 out. No Cauchy-Schwarz shift (caused R10's fp16 underflow).
// mma.sync bf16 3-term hi/lo split; ptxas target sm_103 -> no tcgen05.

#define NTOK 4096
#define DDIM 64
#define NB   4

__device__ __nv_bfloat16 g_hi[(size_t)NB * NTOK * DDIM];   // 4 MB
__device__ __nv_bfloat16 g_lo[(size_t)NB * NTOK * DDIM];   // 4 MB
__device__ float2 g_part[(size_t)NB * NTOK * 64];          // 8 MB (max,sum)
__device__ __half g_E   [(size_t)NB * NTOK * NTOK];        // 128 MB fp16 exp

#define SW128(off) ((off) ^ (((off) >> 3) & 0x70))

// smem: operands Ah@0 Al@16K Bh@32K Bl@40K (to 49152)
// aux:  credm@49152(1K) creds@50176(1K) cmax@51200(256B)
// stage (mirror) reuses [0, 33792)
#define OFF_AL    16384
#define OFF_BH    32768
#define OFF_BL    40960
#define OFF_CREDM 49152
#define OFF_CREDS 50176
#define OFF_CMAX  51200
#define SMEM_BYTES 51712
#define STG_LD 132

__device__ __forceinline__ unsigned smem_u32(const void* p) {
    unsigned a;
    asm("{ .reg .u64 t; cvta.to.shared.u64 t, %1; cvt.u32.u64 %0, t; }"
        : "=r"(a) : "l"(p));
    return a;
}
__device__ __forceinline__ void ldsm4(unsigned* r, unsigned addr) {
    asm volatile("ldmatrix.sync.aligned.m8n8.x4.shared.b16 {%0,%1,%2,%3}, [%4];"
                 : "=r"(r[0]), "=r"(r[1]), "=r"(r[2]), "=r"(r[3]) : "r"(addr));
}
__device__ __forceinline__ void mma16816(float* d, const unsigned* a,
                                         unsigned b0, unsigned b1) {
    asm volatile(
        "mma.sync.aligned.m16n8k16.row.col.f32.bf16.bf16.f32 "
        "{%0,%1,%2,%3}, {%4,%5,%6,%7}, {%8,%9}, {%0,%1,%2,%3};"
        : "+f"(d[0]), "+f"(d[1]), "+f"(d[2]), "+f"(d[3])
        : "r"(a[0]), "r"(a[1]), "r"(a[2]), "r"(a[3]), "r"(b0), "r"(b1));
}

__device__ __forceinline__ void decode_pair(int p, int& ti, int& tj) {
    ti = (int)((65.0f - sqrtf(4225.0f - 8.0f * (float)p)) * 0.5f);
    while (ti * (65 - ti) / 2 > p) ti--;
    while ((ti + 1) * (64 - ti) / 2 <= p) ti++;
    tj = ti + (p - ti * (65 - ti) / 2);
}

// ---------------- split ----------------
__global__ __launch_bounds__(256) void split_bf16(const float* __restrict__ X) {
    size_t i = ((size_t)blockIdx.x * blockDim.x + threadIdx.x) * 4;
    float4 v = *reinterpret_cast<const float4*>(X + i);
    __nv_bfloat162 h01 = __floats2bfloat162_rn(v.x, v.y);
    __nv_bfloat162 h23 = __floats2bfloat162_rn(v.z, v.w);
    __nv_bfloat162 l01 = __floats2bfloat162_rn(v.x - __low2float(h01),
                                               v.y - __high2float(h01));
    __nv_bfloat162 l23 = __floats2bfloat162_rn(v.z - __low2float(h23),
                                               v.w - __high2float(h23));
    *reinterpret_cast<__nv_bfloat162*>(g_hi + i)     = h01;
    *reinterpret_cast<__nv_bfloat162*>(g_hi + i + 2) = h23;
    *reinterpret_cast<__nv_bfloat162*>(g_lo + i)     = l01;
    *reinterpret_cast<__nv_bfloat162*>(g_lo + i + 2) = l23;
}

// ---------------- tile compute ----------------
template<int CH>
__device__ __forceinline__ void load_t(char* dst, const __nv_bfloat16* src, int tid) {
    const uint4* s = reinterpret_cast<const uint4*>(src);
#pragma unroll
    for (int it = 0; it < CH; it++) {
        int i = it * 128 + tid;
        unsigned off = (unsigned)i * 16u;
        *reinterpret_cast<uint4*>(dst + SW128(off)) = s[i];
    }
}

__device__ __forceinline__ void tile_compute(char* smem, unsigned sm, int tid,
                                             int wid, int lane, int ti, int tj,
                                             int half, int b, bool diag,
                                             float acc[2][8][4]) {
    const size_t gti = (size_t)b * NTOK + (size_t)ti * 128;
    const size_t gtj = (size_t)b * NTOK + (size_t)tj * 128 + half * 64;
    load_t<8>(smem,          g_hi + gti * DDIM, tid);
    load_t<8>(smem + OFF_AL, g_lo + gti * DDIM, tid);
    if (!diag) {
        load_t<4>(smem + OFF_BH, g_hi + gtj * DDIM, tid);
        load_t<4>(smem + OFF_BL, g_lo + gtj * DDIM, tid);
    }
    __syncthreads();

#pragma unroll
    for (int mf = 0; mf < 2; mf++)
#pragma unroll
        for (int nf = 0; nf < 8; nf++)
#pragma unroll
            for (int e = 0; e < 4; e++) acc[mf][nf][e] = 0.0f;

    const int mrow0 = wid * 32;
    const int lrow  = lane & 15;
    const int lkoff = (lane >> 4) * 8;
    const unsigned abH = sm, abL = sm + OFF_AL;
    const unsigned bbH = diag ? sm + half * 8192          : sm + OFF_BH;
    const unsigned bbL = diag ? sm + OFF_AL + half * 8192 : sm + OFF_BL;

    unsigned arow[2], axor[2], brow[4], bxor[4];
#pragma unroll
    for (int mf = 0; mf < 2; mf++) {
        arow[mf] = (unsigned)(mrow0 + mf * 16 + lrow) * 128u;
        axor[mf] = (((mrow0 + mf * 16 + lrow) & 7) << 4);
    }
#pragma unroll
    for (int nq = 0; nq < 4; nq++) {
        brow[nq] = (unsigned)(nq * 16 + lrow) * 128u;
        bxor[nq] = (((nq * 16 + lrow) & 7) << 4);
    }

#pragma unroll
    for (int ks = 0; ks < 4; ks++) {
        const unsigned kb = (unsigned)(ks * 16 + lkoff) * 2u;
        unsigned ah[2][4], al[2][4], bh[4][4], bl[4][4];
#pragma unroll
        for (int mf = 0; mf < 2; mf++)
            ldsm4(ah[mf], abH + arow[mf] + (kb ^ axor[mf]));
#pragma unroll
        for (int nq = 0; nq < 4; nq++)
            ldsm4(bh[nq], bbH + brow[nq] + (kb ^ bxor[nq]));
#pragma unroll
        for (int nq = 0; nq < 4; nq++)
#pragma unroll
            for (int mf = 0; mf < 2; mf++) {
                mma16816(acc[mf][nq * 2 + 0], ah[mf], bh[nq][0], bh[nq][2]);
                mma16816(acc[mf][nq * 2 + 1], ah[mf], bh[nq][1], bh[nq][3]);
            }
#pragma unroll
        for (int mf = 0; mf < 2; mf++)
            ldsm4(al[mf], abL + arow[mf] + (kb ^ axor[mf]));
#pragma unroll
        for (int nq = 0; nq < 4; nq++)
            ldsm4(bl[nq], bbL + brow[nq] + (kb ^ bxor[nq]));
#pragma unroll
        for (int nq = 0; nq < 4; nq++)
#pragma unroll
            for (int mf = 0; mf < 2; mf++) {
                mma16816(acc[mf][nq * 2 + 0], ah[mf], bl[nq][0], bl[nq][2]);
                mma16816(acc[mf][nq * 2 + 1], ah[mf], bl[nq][1], bl[nq][3]);
            }
#pragma unroll
        for (int nq = 0; nq < 4; nq++)
#pragma unroll
            for (int mf = 0; mf < 2; mf++) {
                mma16816(acc[mf][nq * 2 + 0], al[mf], bh[nq][0], bh[nq][2]);
                mma16816(acc[mf][nq * 2 + 1], al[mf], bh[nq][1], bh[nq][3]);
            }
    }
}

// ---------------- gemm_exp ----------------
__global__ __launch_bounds__(128, 4) void gemm_exp() {
    int ti, tj;
    decode_pair(blockIdx.x, ti, tj);
    const int half = blockIdx.y, b = blockIdx.z;
    const bool diag = (ti == tj);

    extern __shared__ __align__(1024) char smem[];
    float* stage = reinterpret_cast<float*>(smem);
    const unsigned sm = smem_u32(smem);
    const int tid = threadIdx.x, wid = tid >> 5, lane = tid & 31;

    float acc[2][8][4];
    tile_compute(smem, sm, tid, wid, lane, ti, tj, half, b, diag, acc);

    float* credm = reinterpret_cast<float*>(smem + OFF_CREDM);
    float* creds = reinterpret_cast<float*>(smem + OFF_CREDS);
    float* cmax  = reinterpret_cast<float*>(smem + OFF_CMAX);

    const int mrow0 = wid * 32;
    const int fr = lane >> 2;
    const int fc = (lane & 3) * 2;
    const size_t gti = (size_t)b * NTOK + (size_t)ti * 128;
    const size_t gtj = (size_t)b * NTOK + (size_t)tj * 128 + half * 64;

    // --- row-side: exact 64-col chunk max, fp16 exp store, (max,sum) partial
    {
        float rmx[4];
#pragma unroll
        for (int mf = 0; mf < 2; mf++) {
            float m0 = -1e30f, m1 = -1e30f;
#pragma unroll
            for (int nf = 0; nf < 8; nf++) {
                m0 = fmaxf(m0, fmaxf(acc[mf][nf][0], acc[mf][nf][1]));
                m1 = fmaxf(m1, fmaxf(acc[mf][nf][2], acc[mf][nf][3]));
            }
            rmx[mf * 2] = m0; rmx[mf * 2 + 1] = m1;
        }
#pragma unroll
        for (int k = 0; k < 4; k++) {
            rmx[k] = fmaxf(rmx[k], __shfl_xor_sync(~0u, rmx[k], 1));
            rmx[k] = fmaxf(rmx[k], __shfl_xor_sync(~0u, rmx[k], 2));
        }

        __half* dst = g_E + gti * NTOK + tj * 128 + half * 64;
        float rs[4] = {0.f, 0.f, 0.f, 0.f};
#pragma unroll
        for (int mf = 0; mf < 2; mf++) {
            const int r0 = mrow0 + mf * 16 + fr;
            const float m0 = rmx[mf * 2], m1 = rmx[mf * 2 + 1];
#pragma unroll
            for (int nf = 0; nf < 8; nf++) {
                const int c = nf * 8 + fc;
                float e0 = __expf(acc[mf][nf][0] - m0);
                float e1 = __expf(acc[mf][nf][1] - m0);
                float e2 = __expf(acc[mf][nf][2] - m1);
                float e3 = __expf(acc[mf][nf][3] - m1);
                rs[mf * 2] += e0 + e1; rs[mf * 2 + 1] += e2 + e3;
                *reinterpret_cast<__half2*>(dst + (size_t)r0 * NTOK + c) =
                    __floats2half2_rn(e0, e1);
                *reinterpret_cast<__half2*>(dst + (size_t)(r0 + 8) * NTOK + c) =
                    __floats2half2_rn(e2, e3);
            }
        }
#pragma unroll
        for (int k = 0; k < 4; k++) {
            rs[k] += __shfl_xor_sync(~0u, rs[k], 1);
            rs[k] += __shfl_xor_sync(~0u, rs[k], 2);
        }
        if ((lane & 3) == 0) {
            const int slot = tj * 2 + half;   // in [2*ti, 64)
#pragma unroll
            for (int k = 0; k < 4; k++) {
                int r = mrow0 + (k >> 1) * 16 + fr + (k & 1) * 8;
                g_part[(gti + r) * 64 + slot] = make_float2(rmx[k], rs[k]);
            }
        }
    }

    if (diag) return;

    // --- col-side mirror: tile max over 128 rows, exp stage, split sums ---
    __syncthreads();  // operands dead; aux regions live
    // per-warp column maxima (32 rows each)
#pragma unroll
    for (int nf = 0; nf < 8; nf++) {
        const int c0 = nf * 8 + fc;
        float m0 = fmaxf(fmaxf(acc[0][nf][0], acc[0][nf][2]),
                         fmaxf(acc[1][nf][0], acc[1][nf][2]));
        float m1 = fmaxf(fmaxf(acc[0][nf][1], acc[0][nf][3]),
                         fmaxf(acc[1][nf][1], acc[1][nf][3]));
#pragma unroll
        for (int o = 4; o <= 16; o <<= 1) {
            m0 = fmaxf(m0, __shfl_xor_sync(~0u, m0, o));
            m1 = fmaxf(m1, __shfl_xor_sync(~0u, m1, o));
        }
        if (lane < 4) { credm[wid * 64 + c0] = m0; credm[wid * 64 + c0 + 1] = m1; }
    }
    __syncthreads();
    if (tid < 64)
        cmax[tid] = fmaxf(fmaxf(credm[tid], credm[64 + tid]),
                          fmaxf(credm[128 + tid], credm[192 + tid]));
    __syncthreads();

    // exp with the 128-row tile max; stage fp32; per-warp sums
#pragma unroll
    for (int nf = 0; nf < 8; nf++) {
        const int c0 = nf * 8 + fc;
        const float mc0 = cmax[c0], mc1 = cmax[c0 + 1];
        float p0 = 0.f, p1 = 0.f;
#pragma unroll
        for (int mf = 0; mf < 2; mf++) {
            const int r0 = mrow0 + mf * 16 + fr;
            float e0 = __expf(acc[mf][nf][0] - mc0);
            float e2 = __expf(acc[mf][nf][2] - mc0);
            float e1 = __expf(acc[mf][nf][1] - mc1);
            float e3 = __expf(acc[mf][nf][3] - mc1);
            p0 += e0 + e2; p1 += e1 + e3;
            stage[(size_t)c0 * STG_LD + r0]           = e0;
            stage[(size_t)c0 * STG_LD + r0 + 8]       = e2;
            stage[(size_t)(c0 + 1) * STG_LD + r0]     = e1;
            stage[(size_t)(c0 + 1) * STG_LD + r0 + 8] = e3;
        }
#pragma unroll
        for (int o = 4; o <= 16; o <<= 1) {
            p0 += __shfl_xor_sync(~0u, p0, o);
            p1 += __shfl_xor_sync(~0u, p1, o);
        }
        if (lane < 4) { creds[wid * 64 + c0] = p0; creds[wid * 64 + c0 + 1] = p1; }
    }
    __syncthreads();
    if (tid < 64) {
        // warps 0,1 -> A-rows [0,64) -> slot 2ti; warps 2,3 -> slot 2ti+1
        float sLo = creds[tid] + creds[64 + tid];
        float sHi = creds[128 + tid] + creds[192 + tid];
        float m = cmax[tid];
        g_part[(gtj + tid) * 64 + 2 * ti]     = make_float2(m, sLo);
        g_part[(gtj + tid) * 64 + 2 * ti + 1] = make_float2(m, sHi);
    }
    // fp16 copy-out (coalesced)
    {
        __half* dst = g_E + gtj * NTOK + ti * 128;
        const int c4 = (tid & 31) * 4, rq = tid >> 5;
#pragma unroll
        for (int it = 0; it < 16; it++) {
            const int sr = rq + it * 4;
            float4 v = *reinterpret_cast<const float4*>(
                stage + (size_t)sr * STG_LD + c4);
            *reinterpret_cast<__half2*>(dst + (size_t)sr * NTOK + c4) =
                __floats2half2_rn(v.x, v.y);
            *reinterpret_cast<__half2*>(dst + (size_t)sr * NTOK + c4 + 2) =
                __floats2half2_rn(v.z, v.w);
        }
    }
}

// ---------------- scale_rows: LSE merge + stream out ----------------
__global__ __launch_bounds__(256) void scale_rows(float* __restrict__ out) {
    const size_t row = blockIdx.x;
    const int tid = threadIdx.x, lane = tid & 31;
    const float2* P = g_part + row * 64;

    __shared__ float fac[64];
    __shared__ float redm[2], reds[2];

    if (tid < 64) {
        float m = P[tid].x;
#pragma unroll
        for (int o = 16; o > 0; o >>= 1) m = fmaxf(m, __shfl_xor_sync(~0u, m, o));
        if (lane == 0) redm[tid >> 5] = m;
    }
    __syncthreads();
    const float M = fmaxf(redm[0], redm[1]);
    if (tid < 64) {
        float e = __expf(P[tid].x - M);
        fac[tid] = e;
        float c = P[tid].y * e;
#pragma unroll
        for (int o = 16; o > 0; o >>= 1) c += __shfl_xor_sync(~0u, c, o);
        if (lane == 0) reds[tid >> 5] = c;
    }
    __syncthreads();
    const float invS = 1.0f / (reds[0] + reds[1]);

    const __half* src = g_E + row * NTOK;
    float* dst = out + row * NTOK;
#pragma unroll
    for (int p = 0; p < 2; p++) {
        const int o = p * 2048 + tid * 8;
        const float f = fac[o >> 6] * invS;
        uint4 raw = __ldcs(reinterpret_cast<const uint4*>(src + o));
        const __half2* h = reinterpret_cast<const __half2*>(&raw);
        float2 f0 = __half22float2(h[0]);
        float2 f1 = __half22float2(h[1]);
        float2 f2 = __half22float2(h[2]);
        float2 f3 = __half22float2(h[3]);
        __stcs(reinterpret_cast<float4*>(dst + o),
               make_float4(f0.x * f, f0.y * f, f1.x * f, f1.y * f));
        __stcs(reinterpret_cast<float4*>(dst + o + 4),
               make_float4(f2.x * f, f2.y * f, f3.x * f, f3.y * f));
    }
}

extern "C" void kernel_launch(void* const* d_in, const int* in_sizes, int n_in,
                              void* d_out, int out_size) {
    const float* X = (const float*)d_in[0];
    float* out     = (float*)d_out;
    (void)in_sizes; (void)n_in; (void)out_size;

    cudaFuncSetAttribute(gemm_exp, cudaFuncAttributeMaxDynamicSharedMemorySize,
                         SMEM_BYTES);

    split_bf16<<<1024, 256>>>(X);
    gemm_exp<<<dim3(528, 2, NB), 128, SMEM_BYTES>>>();
    scale_rows<<<NB * NTOK, 256>>>(out);
}